// round 14
// baseline (speedup 1.0000x reference)
#include <cuda_runtime.h>
#include <cstdint>

#define TT 25
#define PH 132   // smem pitch (floats): 132 % 32 == 4 -> conflict-free frags

__device__ __align__(16) float g_Wk2[128 * 512];  // input weights, lane-major frag layout
__device__ __align__(16) float g_Wr2[128 * 512];  // recurrent weights, lane-major frag layout
__device__ __align__(16) float g_We[256 * 128];   // output weights (frag-ordered)
__device__ float g_Ho[(size_t)16384 * 128];       // h at t = len-1
__device__ float g_XW[(size_t)16384 * TT * 512];  // x@Wk in accumulator-fragment layout

__device__ __forceinline__ uint32_t tf32r(float v) {
    uint32_t t; asm("cvt.rna.tf32.f32 %0, %1;" : "=r"(t) : "f"(v)); return t;
}
__device__ __forceinline__ float tf32f(float v) { return __uint_as_float(tf32r(v)); }
__device__ __forceinline__ float tanhap(float x) {
    float r; asm("tanh.approx.f32 %0, %1;" : "=f"(r) : "f"(x)); return r;
}
__device__ __forceinline__ float sig_a(float x) { return fmaf(0.5f, tanhap(0.5f * x), 0.5f); }
__device__ __forceinline__ uint32_t u32(float v) { return __float_as_uint(v); }
__device__ __forceinline__ uint32_t smem_u32(const void* p) {
    uint32_t a;
    asm("{.reg .u64 t; cvta.to.shared.u64 t, %1; cvt.u32.u64 %0, t;}" : "=r"(a) : "l"(p));
    return a;
}
__device__ __forceinline__ void cp16(uint32_t dst, const float* src) {
    asm volatile("cp.async.ca.shared.global [%0],[%1],16;" :: "r"(dst), "l"(src) : "memory");
}
#define CP_COMMIT() asm volatile("cp.async.commit_group;" ::: "memory")
#define CP_WAIT0()  asm volatile("cp.async.wait_group 0;" ::: "memory")
#define CP_WAIT1()  asm volatile("cp.async.wait_group 1;" ::: "memory")

__device__ __forceinline__ void mma8(float* d, const uint32_t* a, uint32_t b0, uint32_t b1) {
    asm volatile("mma.sync.aligned.m16n8k8.row.col.f32.tf32.tf32.f32 "
        "{%0,%1,%2,%3},{%4,%5,%6,%7},{%8,%9},{%0,%1,%2,%3};"
        : "+f"(d[0]), "+f"(d[1]), "+f"(d[2]), "+f"(d[3])
        : "r"(a[0]), "r"(a[1]), "r"(a[2]), "r"(a[3]), "r"(b0), "r"(b1));
}

// Lane-major frag layout for K=128 weights: flat f = (((c*4+q)*8+nw)*32+lane)*4+e.
// q=0 -> B0[e], q=1 -> B0[e+4], q=2 -> B1[e], q=3 -> B1[e+4].
// Gate-interleaved logical col: n' = nw*64 + j*8 + ly, source col = (n'&3)*128 + (n'>>2).
__global__ void prep_kernel(const float* __restrict__ Wk, const float* __restrict__ Wr,
                            const float* __restrict__ Ws, const float* __restrict__ Wn) {
    int f = blockIdx.x * blockDim.x + threadIdx.x;   // 65536 threads
    {
        int c = f >> 12, q = (f >> 10) & 3, nw = (f >> 7) & 7, lane = (f >> 2) & 31, e = f & 3;
        int ly = lane >> 2, kx = lane & 3;
        int k = c * 8 + kx + ((q >> 1) << 2);
        int j = (q & 1) ? e + 4 : e;
        int n = nw * 64 + j * 8 + ly;
        int col = (n & 3) * 128 + (n >> 2);
        g_Wk2[f] = tf32f(Wk[k * 512 + col]);
        g_Wr2[f] = tf32f(Wr[k * 512 + col]);
    }
    if (f < 256 * 128) {
        int k = f >> 7, pos = f & 127;
        int nw = pos >> 5, r = pos & 31, ly = r >> 2, j = r & 3;
        int n = nw * 32 + j * 8 + ly;
        float v = (k < 128) ? Ws[k * 128 + n] : Wn[(k - 128) * 128 + n];
        g_We[k * 128 + nw * 32 + ly * 4 + j] = tf32f(v);
    }
}

#define SMEM_DYN ((3 * 64 * PH + 512 + 64) * 4)

// Fused kernel: per-CTA phases — A: xW prologue (own 64 rows, all t, no cross-CTA dep),
// B: LSTM recurrence, C: output GEMM. 256 CTAs x 256 thr, 2 CTAs/SM.
__global__ __launch_bounds__(256, 2)
void lstm_fused(const float* __restrict__ self_vecs, const float* __restrict__ neig,
                const float* __restrict__ bias, float* __restrict__ out) {
    extern __shared__ float sm[];
    // phase A: sm[0 .. 2*64*PH) = x double buffer
    // phase B: sm[0 .. 3*64*PH) = H0 | H1 | C
    float* biasP = sm + 3 * 64 * PH;       // [512] permuted bias (disjoint from both phases)
    int* LEN = (int*)(biasP + 512);

    const int tid = threadIdx.x, wid = tid >> 5, lane = tid & 31;
    const int ly = lane >> 2, kx = lane & 3;
    const int bb = blockIdx.x, b0 = bb * 64;
    const uint32_t Xs = smem_u32(sm);

    for (int i = tid; i < 512; i += 256) biasP[i] = bias[(i & 3) * 128 + (i >> 2)];

    // exact sequence lengths: warp w -> rows w*8..w*8+7 (also warms L2 for phase A)
    #pragma unroll
    for (int j = 0; j < 8; j++) {
        int r = wid * 8 + j;
        const float4* xp = (const float4*)(neig + (size_t)(b0 + r) * TT * 128) + lane;
        int cnt = 0;
        for (int t = 0; t < TT; t++) {
            float4 v = xp[t * 32];
            bool nz = v.x != 0.f || v.y != 0.f || v.z != 0.f || v.w != 0.f;
            cnt += (__ballot_sync(~0u, nz) != 0u);
        }
        if (lane == 0) LEN[r] = cnt ? cnt : 1;
    }

    const int nw = wid;                    // 8 warps, each owns 64 output cols
    const bool evenlane = (kx & 1) == 0;

    // ---------------- phase A: g_XW = x_t @ Wk for own 64 rows, all t ----------------
    #pragma unroll
    for (int j2 = 0; j2 < 8; j2++) {       // prefetch t=0 into buf 0
        int i = tid + j2 * 256;
        int r = i >> 5, q = i & 31;
        cp16(Xs + (uint32_t)(r * PH + q * 4) * 4u,
             neig + ((size_t)(b0 + r) * TT) * 128 + q * 4);
    }
    CP_COMMIT();

    #pragma unroll 1
    for (int t = 0; t < TT; t++) {
        if (t < TT - 1) {
            const uint32_t dstb = Xs + (uint32_t)(((t + 1) & 1) * 64 * PH) * 4u;
            #pragma unroll
            for (int j2 = 0; j2 < 8; j2++) {
                int i = tid + j2 * 256;
                int r = i >> 5, q = i & 31;
                cp16(dstb + (uint32_t)(r * PH + q * 4) * 4u,
                     neig + ((size_t)(b0 + r) * TT + t + 1) * 128 + q * 4);
            }
            CP_COMMIT();
            CP_WAIT1();
        } else {
            CP_WAIT0();
        }
        __syncthreads();
        const float* Xb = sm + (t & 1) * 64 * PH;

        #pragma unroll 1
        for (int p = 0; p < 2; p++) {
            const int R0 = p * 32;
            float acc[2][8][4];
            #pragma unroll
            for (int m = 0; m < 2; m++)
                #pragma unroll
                for (int j = 0; j < 8; j++)
                    #pragma unroll
                    for (int e = 0; e < 4; e++) acc[m][j][e] = 0.f;

            const float* wp = g_Wk2 + nw * 128 + lane * 4;
            float4 n0 = *(const float4*)wp,            n1 = *(const float4*)(wp + 1024);
            float4 n2 = *(const float4*)(wp + 2048),   n3 = *(const float4*)(wp + 3072);
            #pragma unroll 1
            for (int c = 0; c < 16; c++) {
                float4 b0v = n0, b1v = n1, b2v = n2, b3v = n3;
                if (c < 15) {
                    const float* np = wp + (c + 1) * 4096;
                    n0 = *(const float4*)np;            n1 = *(const float4*)(np + 1024);
                    n2 = *(const float4*)(np + 2048);   n3 = *(const float4*)(np + 3072);
                }
                const float* ap = Xb + (R0 + ly) * PH + c * 8 + kx;
                uint32_t af0[4] = {u32(ap[0]), u32(ap[8 * PH]), u32(ap[4]), u32(ap[8 * PH + 4])};
                uint32_t af1[4] = {u32(ap[16 * PH]), u32(ap[24 * PH]),
                                   u32(ap[16 * PH + 4]), u32(ap[24 * PH + 4])};
                uint32_t B0[8] = {u32(b0v.x), u32(b0v.y), u32(b0v.z), u32(b0v.w),
                                  u32(b1v.x), u32(b1v.y), u32(b1v.z), u32(b1v.w)};
                uint32_t B1[8] = {u32(b2v.x), u32(b2v.y), u32(b2v.z), u32(b2v.w),
                                  u32(b3v.x), u32(b3v.y), u32(b3v.z), u32(b3v.w)};
                #pragma unroll
                for (int j = 0; j < 8; j++) {
                    mma8(acc[0][j], af0, B0[j], B1[j]);
                    mma8(acc[1][j], af1, B0[j], B1[j]);
                }
            }
            float* op = g_XW + ((((size_t)bb * TT + t) * 2 + p) * 8 + nw) * 2048 + lane * 4;
            #pragma unroll
            for (int i = 0; i < 16; i++)
                *(float4*)(op + i * 128) =
                    make_float4(acc[i >> 3][i & 7][0], acc[i >> 3][i & 7][1],
                                acc[i >> 3][i & 7][2], acc[i >> 3][i & 7][3]);
        }
        __syncthreads();   // all reads of this X buffer done before it is refilled
    }

    // ---------------- phase B: recurrence (reuses smem as H0|H1|C) ----------------
    float* H0 = sm;
    float* H1 = sm + 64 * PH;
    float* C  = sm + 2 * 64 * PH;
    for (int i = tid; i < 64 * 128; i += 256) H0[(i >> 7) * PH + (i & 127)] = 0.f;
    for (int i = tid; i < 64 * PH; i += 256) C[i] = 0.f;

    for (int t = 0; t < TT; t++) {
        __syncthreads();   // h writes of step t-1 visible
        const float* hc = (t & 1) ? H1 : H0;
        float*       hn = (t & 1) ? H0 : H1;

        #pragma unroll 1
        for (int p = 0; p < 2; p++) {      // two 32-row m-passes within the 64
            const int R0 = p * 32;
            float acc[2][8][4];
            {   // acc init = own precomputed x_t@Wk fragment
                const float* xp = g_XW + ((((size_t)bb * TT + t) * 2 + p) * 8 + nw) * 2048
                                + lane * 4;
                #pragma unroll
                for (int i = 0; i < 16; i++) {
                    float4 v = *(const float4*)(xp + i * 128);
                    acc[i >> 3][i & 7][0] = v.x; acc[i >> 3][i & 7][1] = v.y;
                    acc[i >> 3][i & 7][2] = v.z; acc[i >> 3][i & 7][3] = v.w;
                }
            }
            const float* wp = g_Wr2 + nw * 128 + lane * 4;
            float4 n0 = *(const float4*)wp,            n1 = *(const float4*)(wp + 1024);
            float4 n2 = *(const float4*)(wp + 2048),   n3 = *(const float4*)(wp + 3072);
            #pragma unroll 1
            for (int c = 0; c < 16; c++) {
                float4 b0v = n0, b1v = n1, b2v = n2, b3v = n3;
                if (c < 15) {
                    const float* np = wp + (c + 1) * 4096;
                    n0 = *(const float4*)np;            n1 = *(const float4*)(np + 1024);
                    n2 = *(const float4*)(np + 2048);   n3 = *(const float4*)(np + 3072);
                }
                const float* ap = hc + (R0 + ly) * PH + c * 8 + kx;
                uint32_t af0[4] = {u32(ap[0]), u32(ap[8 * PH]), u32(ap[4]), u32(ap[8 * PH + 4])};
                uint32_t af1[4] = {u32(ap[16 * PH]), u32(ap[24 * PH]),
                                   u32(ap[16 * PH + 4]), u32(ap[24 * PH + 4])};
                uint32_t B0[8] = {u32(b0v.x), u32(b0v.y), u32(b0v.z), u32(b0v.w),
                                  u32(b1v.x), u32(b1v.y), u32(b1v.z), u32(b1v.w)};
                uint32_t B1[8] = {u32(b2v.x), u32(b2v.y), u32(b2v.z), u32(b2v.w),
                                  u32(b3v.x), u32(b3v.y), u32(b3v.z), u32(b3v.w)};
                #pragma unroll
                for (int j = 0; j < 8; j++) {
                    mma8(acc[0][j], af0, B0[j], B1[j]);
                    mma8(acc[1][j], af1, B0[j], B1[j]);
                }
            }

            // ---- gate epilogue straight after own GEMM (writes hn, no hazard) ----
            #pragma unroll
            for (int mt = 0; mt < 2; mt++) {
                #pragma unroll
                for (int j = 0; j < 8; j++) {
                    const int nn0 = nw * 64 + j * 8 + 2 * kx;
                    const float bz0 = biasP[nn0], bz1 = biasP[nn0 + 1];
                    float z00 = acc[mt][j][0] + bz0;
                    float z01 = acc[mt][j][1] + bz1;
                    float z10 = acc[mt][j][2] + bz0;
                    float z11 = acc[mt][j][3] + bz1;
                    float a00, a01, a10, a11;
                    if (evenlane) { a00 = sig_a(z00);  a01 = sig_a(z01);
                                    a10 = sig_a(z10);  a11 = sig_a(z11); }
                    else          { a00 = tanhap(z00); a01 = sig_a(z01);
                                    a10 = tanhap(z10); a11 = sig_a(z11); }
                    float s1 = evenlane ? a10 : a00;
                    float s2 = evenlane ? a11 : a01;
                    float r1 = __shfl_xor_sync(~0u, s1, 1);
                    float r2 = __shfl_xor_sync(~0u, s2, 1);
                    float iv, fv, gv, ov; int rr;
                    if (evenlane) { iv = a00; fv = a01; gv = r1; ov = r2; rr = R0 + mt * 16 + ly; }
                    else          { iv = r1;  fv = r2;  gv = a10; ov = a11; rr = R0 + mt * 16 + 8 + ly; }
                    const int uu = nw * 16 + j * 2 + (kx >> 1);
                    float cc = fv * C[rr * PH + uu] + iv * gv;
                    C[rr * PH + uu] = cc;
                    float h = ov * tanhap(cc);
                    hn[rr * PH + uu] = tf32f(h);
                    if (t == LEN[rr] - 1) g_Ho[(size_t)(b0 + rr) * 128 + uu] = h;
                }
            }
        }
    }
    __syncthreads();

    // ---------------- phase C: out = relu([self | h_sel] @ We) ----------------
    for (int i = tid; i < 64 * 32; i += 256) {
        int r = i >> 5, q = i & 31;
        float4 v = *(const float4*)(self_vecs + (size_t)(b0 + r) * 128 + q * 4);
        *(float4*)(H0 + r * PH + q * 4) =
            make_float4(tf32f(v.x), tf32f(v.y), tf32f(v.z), tf32f(v.w));
        float4 h = *(const float4*)(g_Ho + (size_t)(b0 + r) * 128 + q * 4);
        *(float4*)(H1 + r * PH + q * 4) =
            make_float4(tf32f(h.x), tf32f(h.y), tf32f(h.z), tf32f(h.w));
    }
    __syncthreads();

    const int mw2 = wid & 1, nw2 = wid >> 1;   // 2m x 4n warp grid over 64 rows
    const int R2 = mw2 * 32;
    float ac2[2][4][4];
    #pragma unroll
    for (int m = 0; m < 2; m++)
        #pragma unroll
        for (int j = 0; j < 4; j++)
            #pragma unroll
            for (int e = 0; e < 4; e++) ac2[m][j][e] = 0.f;

    #pragma unroll 1
    for (int c = 0; c < 32; c++) {
        const float* bp = g_We + (c * 8 + kx) * 128 + nw2 * 32 + ly * 4;
        float4 q0 = *(const float4*)bp;
        float4 q1 = *(const float4*)(bp + 4 * 128);
        uint32_t B0[4] = {u32(q0.x), u32(q0.y), u32(q0.z), u32(q0.w)};
        uint32_t B1[4] = {u32(q1.x), u32(q1.y), u32(q1.z), u32(q1.w)};
        const float* base = (c < 16) ? H0 : H1;
        const int cc = c & 15;
        const float* ap = base + (R2 + ly) * PH + cc * 8 + kx;
        uint32_t af0[4] = {u32(ap[0]), u32(ap[8 * PH]), u32(ap[4]), u32(ap[8 * PH + 4])};
        uint32_t af1[4] = {u32(ap[16 * PH]), u32(ap[24 * PH]),
                           u32(ap[16 * PH + 4]), u32(ap[24 * PH + 4])};
        #pragma unroll
        for (int j = 0; j < 4; j++) {
            mma8(ac2[0][j], af0, B0[j], B1[j]);
            mma8(ac2[1][j], af1, B0[j], B1[j]);
        }
    }
    #pragma unroll
    for (int mt = 0; mt < 2; mt++)
        #pragma unroll
        for (int j = 0; j < 4; j++)
            #pragma unroll
            for (int rh = 0; rh < 2; rh++) {
                int row = R2 + mt * 16 + rh * 8 + ly;
                int col = nw2 * 32 + j * 8 + 2 * kx;
                float2 o;
                o.x = fmaxf(ac2[mt][j][rh * 2], 0.f);
                o.y = fmaxf(ac2[mt][j][rh * 2 + 1], 0.f);
                *(float2*)(out + (size_t)(b0 + row) * 128 + col) = o;
            }
}

extern "C" void kernel_launch(void* const* d_in, const int* in_sizes, int n_in,
                              void* d_out, int out_size) {
    prep_kernel<<<128, 512>>>((const float*)d_in[2], (const float*)d_in[3],
                              (const float*)d_in[5], (const float*)d_in[6]);
    cudaFuncSetAttribute(lstm_fused, cudaFuncAttributeMaxDynamicSharedMemorySize, SMEM_DYN);
    lstm_fused<<<256, 256, SMEM_DYN>>>((const float*)d_in[0], (const float*)d_in[1],
                                       (const float*)d_in[4], (float*)d_out);
}

// round 15
// speedup vs baseline: 1.1405x; 1.1405x over previous
#include <cuda_runtime.h>
#include <cuda_fp16.h>
#include <cstdint>

#define TT 25
#define PH 132   // smem pitch (floats): 132 % 32 == 4 -> conflict-free frags

__device__ __align__(16) float g_Wk2[128 * 512];  // input weights, lane-major frag layout
__device__ __align__(16) float g_Wr2[128 * 512];  // recurrent weights, lane-major frag layout
__device__ __align__(16) float g_We[256 * 128];   // output weights (frag-ordered)
__device__ float g_Ho[(size_t)16384 * 128];       // h at t = len-1
__device__ __align__(16) __half g_XW[(size_t)16384 * TT * 512];  // x@Wk, fp16 frag layout

__device__ __forceinline__ uint32_t tf32r(float v) {
    uint32_t t; asm("cvt.rna.tf32.f32 %0, %1;" : "=r"(t) : "f"(v)); return t;
}
__device__ __forceinline__ float tf32f(float v) { return __uint_as_float(tf32r(v)); }
__device__ __forceinline__ float tanhap(float x) {
    float r; asm("tanh.approx.f32 %0, %1;" : "=f"(r) : "f"(x)); return r;
}
__device__ __forceinline__ float sig_a(float x) { return fmaf(0.5f, tanhap(0.5f * x), 0.5f); }
__device__ __forceinline__ uint32_t u32(float v) { return __float_as_uint(v); }
__device__ __forceinline__ uint32_t smem_u32(const void* p) {
    uint32_t a;
    asm("{.reg .u64 t; cvta.to.shared.u64 t, %1; cvt.u32.u64 %0, t;}" : "=r"(a) : "l"(p));
    return a;
}
__device__ __forceinline__ void cp16(uint32_t dst, const float* src) {
    asm volatile("cp.async.ca.shared.global [%0],[%1],16;" :: "r"(dst), "l"(src) : "memory");
}
#define CP_COMMIT() asm volatile("cp.async.commit_group;" ::: "memory")
#define CP_WAIT0()  asm volatile("cp.async.wait_group 0;" ::: "memory")
#define CP_WAIT1()  asm volatile("cp.async.wait_group 1;" ::: "memory")

__device__ __forceinline__ void mma8(float* d, const uint32_t* a, uint32_t b0, uint32_t b1) {
    asm volatile("mma.sync.aligned.m16n8k8.row.col.f32.tf32.tf32.f32 "
        "{%0,%1,%2,%3},{%4,%5,%6,%7},{%8,%9},{%0,%1,%2,%3};"
        : "+f"(d[0]), "+f"(d[1]), "+f"(d[2]), "+f"(d[3])
        : "r"(a[0]), "r"(a[1]), "r"(a[2]), "r"(a[3]), "r"(b0), "r"(b1));
}

// Lane-major frag layout for K=128 weights: flat f = (((c*4+q)*8+nw)*32+lane)*4+e.
// Gate-interleaved logical col: n' = nw*64 + j*8 + ly, source col = (n'&3)*128 + (n'>>2).
__global__ void prep_kernel(const float* __restrict__ Wk, const float* __restrict__ Wr,
                            const float* __restrict__ Ws, const float* __restrict__ Wn) {
    int f = blockIdx.x * blockDim.x + threadIdx.x;   // 65536 threads
    {
        int c = f >> 12, q = (f >> 10) & 3, nw = (f >> 7) & 7, lane = (f >> 2) & 31, e = f & 3;
        int ly = lane >> 2, kx = lane & 3;
        int k = c * 8 + kx + ((q >> 1) << 2);
        int j = (q & 1) ? e + 4 : e;
        int n = nw * 64 + j * 8 + ly;
        int col = (n & 3) * 128 + (n >> 2);
        g_Wk2[f] = tf32f(Wk[k * 512 + col]);
        g_Wr2[f] = tf32f(Wr[k * 512 + col]);
    }
    if (f < 256 * 128) {
        int k = f >> 7, pos = f & 127;
        int nw = pos >> 5, r = pos & 31, ly = r >> 2, j = r & 3;
        int n = nw * 32 + j * 8 + ly;
        float v = (k < 128) ? Ws[k * 128 + n] : Wn[(k - 128) * 128 + n];
        g_We[k * 128 + nw * 32 + ly * 4 + j] = tf32f(v);
    }
}

#define SMEM_DYN ((3 * 64 * PH + 512 + 64) * 4)

// Fused kernel: A: xW prologue (own 64 rows, all t; LEN from smem tiles),
// B: LSTM recurrence, C: output GEMM. 256 CTAs x 256 thr, 2 CTAs/SM.
__global__ __launch_bounds__(256, 2)
void lstm_fused(const float* __restrict__ self_vecs, const float* __restrict__ neig,
                const float* __restrict__ bias, float* __restrict__ out) {
    extern __shared__ float sm[];
    float* biasP = sm + 3 * 64 * PH;       // [512] permuted bias (disjoint from phases)
    int* LEN = (int*)(biasP + 512);

    const int tid = threadIdx.x, wid = tid >> 5, lane = tid & 31;
    const int ly = lane >> 2, kx = lane & 3;
    const int bb = blockIdx.x, b0 = bb * 64;
    const uint32_t Xs = smem_u32(sm);

    for (int i = tid; i < 512; i += 256) biasP[i] = bias[(i & 3) * 128 + (i >> 2)];

    const int nw = wid;                    // 8 warps, each owns 64 output cols
    const bool evenlane = (kx & 1) == 0;

    // ---------------- phase A: g_XW = x_t @ Wk for own 64 rows, all t ----------------
    #pragma unroll
    for (int j2 = 0; j2 < 8; j2++) {       // prefetch t=0 into buf 0
        int i = tid + j2 * 256;
        int r = i >> 5, q = i & 31;
        cp16(Xs + (uint32_t)(r * PH + q * 4) * 4u,
             neig + ((size_t)(b0 + r) * TT) * 128 + q * 4);
    }
    CP_COMMIT();

    int cnt[8];
    #pragma unroll
    for (int j = 0; j < 8; j++) cnt[j] = 0;

    #pragma unroll 1
    for (int t = 0; t < TT; t++) {
        if (t < TT - 1) {
            const uint32_t dstb = Xs + (uint32_t)(((t + 1) & 1) * 64 * PH) * 4u;
            #pragma unroll
            for (int j2 = 0; j2 < 8; j2++) {
                int i = tid + j2 * 256;
                int r = i >> 5, q = i & 31;
                cp16(dstb + (uint32_t)(r * PH + q * 4) * 4u,
                     neig + ((size_t)(b0 + r) * TT + t + 1) * 128 + q * 4);
            }
            CP_COMMIT();
            CP_WAIT1();
        } else {
            CP_WAIT0();
        }
        __syncthreads();
        const float* Xb = sm + (t & 1) * 64 * PH;

        // LEN from the smem tile: warp w checks rows w*8..w*8+7 (exact any-nonzero)
        #pragma unroll
        for (int j = 0; j < 8; j++) {
            const float* rp = Xb + (wid * 8 + j) * PH + lane;
            bool nz = (rp[0] != 0.f) || (rp[32] != 0.f) || (rp[64] != 0.f) || (rp[96] != 0.f);
            cnt[j] += (__ballot_sync(~0u, nz) != 0u);
        }

        #pragma unroll 1
        for (int p = 0; p < 2; p++) {
            const int R0 = p * 32;
            float acc[2][8][4];
            #pragma unroll
            for (int m = 0; m < 2; m++)
                #pragma unroll
                for (int j = 0; j < 8; j++)
                    #pragma unroll
                    for (int e = 0; e < 4; e++) acc[m][j][e] = 0.f;

            const float* wp = g_Wk2 + nw * 128 + lane * 4;
            float4 n0 = *(const float4*)wp,            n1 = *(const float4*)(wp + 1024);
            float4 n2 = *(const float4*)(wp + 2048),   n3 = *(const float4*)(wp + 3072);
            #pragma unroll 1
            for (int c = 0; c < 16; c++) {
                float4 b0v = n0, b1v = n1, b2v = n2, b3v = n3;
                if (c < 15) {
                    const float* np = wp + (c + 1) * 4096;
                    n0 = *(const float4*)np;            n1 = *(const float4*)(np + 1024);
                    n2 = *(const float4*)(np + 2048);   n3 = *(const float4*)(np + 3072);
                }
                const float* ap = Xb + (R0 + ly) * PH + c * 8 + kx;
                uint32_t af0[4] = {u32(ap[0]), u32(ap[8 * PH]), u32(ap[4]), u32(ap[8 * PH + 4])};
                uint32_t af1[4] = {u32(ap[16 * PH]), u32(ap[24 * PH]),
                                   u32(ap[16 * PH + 4]), u32(ap[24 * PH + 4])};
                uint32_t B0[8] = {u32(b0v.x), u32(b0v.y), u32(b0v.z), u32(b0v.w),
                                  u32(b1v.x), u32(b1v.y), u32(b1v.z), u32(b1v.w)};
                uint32_t B1[8] = {u32(b2v.x), u32(b2v.y), u32(b2v.z), u32(b2v.w),
                                  u32(b3v.x), u32(b3v.y), u32(b3v.z), u32(b3v.w)};
                #pragma unroll
                for (int j = 0; j < 8; j++) {
                    mma8(acc[0][j], af0, B0[j], B1[j]);
                    mma8(acc[1][j], af1, B0[j], B1[j]);
                }
            }
            // store fragments as fp16 (uint2 = 4 halves per slot)
            __half* op = g_XW + ((((size_t)bb * TT + t) * 2 + p) * 8 + nw) * 2048 + lane * 4;
            #pragma unroll
            for (int i = 0; i < 16; i++) {
                __half2 h0 = __floats2half2_rn(acc[i >> 3][i & 7][0], acc[i >> 3][i & 7][1]);
                __half2 h1 = __floats2half2_rn(acc[i >> 3][i & 7][2], acc[i >> 3][i & 7][3]);
                uint2 v;
                v.x = *(uint32_t*)&h0; v.y = *(uint32_t*)&h1;
                *(uint2*)(op + i * 128) = v;
            }
        }
        __syncthreads();   // all reads of this X buffer done before it is refilled
    }

    // write LEN (uniform across warp; lane 0 writes)
    if (lane == 0) {
        #pragma unroll
        for (int j = 0; j < 8; j++) LEN[wid * 8 + j] = cnt[j] ? cnt[j] : 1;
    }

    // ---------------- phase B: recurrence (reuses smem as H0|H1|C) ----------------
    float* H0 = sm;
    float* H1 = sm + 64 * PH;
    float* C  = sm + 2 * 64 * PH;
    for (int i = tid; i < 64 * 128; i += 256) H0[(i >> 7) * PH + (i & 127)] = 0.f;
    for (int i = tid; i < 64 * PH; i += 256) C[i] = 0.f;

    for (int t = 0; t < TT; t++) {
        __syncthreads();   // h writes of step t-1 (and LEN/zeroing) visible
        const float* hc = (t & 1) ? H1 : H0;
        float*       hn = (t & 1) ? H0 : H1;

        #pragma unroll 1
        for (int p = 0; p < 2; p++) {      // two 32-row m-passes within the 64
            const int R0 = p * 32;
            float acc[2][8][4];
            {   // acc init = own precomputed x_t@Wk fragment (fp16 -> fp32)
                const __half* xp = g_XW + ((((size_t)bb * TT + t) * 2 + p) * 8 + nw) * 2048
                                + lane * 4;
                #pragma unroll
                for (int i = 0; i < 16; i++) {
                    uint2 v = *(const uint2*)(xp + i * 128);
                    float2 f0 = __half22float2(*(__half2*)&v.x);
                    float2 f1 = __half22float2(*(__half2*)&v.y);
                    acc[i >> 3][i & 7][0] = f0.x; acc[i >> 3][i & 7][1] = f0.y;
                    acc[i >> 3][i & 7][2] = f1.x; acc[i >> 3][i & 7][3] = f1.y;
                }
            }
            const float* wp = g_Wr2 + nw * 128 + lane * 4;
            float4 n0 = *(const float4*)wp,            n1 = *(const float4*)(wp + 1024);
            float4 n2 = *(const float4*)(wp + 2048),   n3 = *(const float4*)(wp + 3072);
            #pragma unroll 1
            for (int c = 0; c < 16; c++) {
                float4 b0v = n0, b1v = n1, b2v = n2, b3v = n3;
                if (c < 15) {
                    const float* np = wp + (c + 1) * 4096;
                    n0 = *(const float4*)np;            n1 = *(const float4*)(np + 1024);
                    n2 = *(const float4*)(np + 2048);   n3 = *(const float4*)(np + 3072);
                }
                const float* ap = hc + (R0 + ly) * PH + c * 8 + kx;
                uint32_t af0[4] = {u32(ap[0]), u32(ap[8 * PH]), u32(ap[4]), u32(ap[8 * PH + 4])};
                uint32_t af1[4] = {u32(ap[16 * PH]), u32(ap[24 * PH]),
                                   u32(ap[16 * PH + 4]), u32(ap[24 * PH + 4])};
                uint32_t B0[8] = {u32(b0v.x), u32(b0v.y), u32(b0v.z), u32(b0v.w),
                                  u32(b1v.x), u32(b1v.y), u32(b1v.z), u32(b1v.w)};
                uint32_t B1[8] = {u32(b2v.x), u32(b2v.y), u32(b2v.z), u32(b2v.w),
                                  u32(b3v.x), u32(b3v.y), u32(b3v.z), u32(b3v.w)};
                #pragma unroll
                for (int j = 0; j < 8; j++) {
                    mma8(acc[0][j], af0, B0[j], B1[j]);
                    mma8(acc[1][j], af1, B0[j], B1[j]);
                }
            }

            // ---- gate epilogue straight after own GEMM (writes hn, no hazard) ----
            #pragma unroll
            for (int mt = 0; mt < 2; mt++) {
                #pragma unroll
                for (int j = 0; j < 8; j++) {
                    const int nn0 = nw * 64 + j * 8 + 2 * kx;
                    const float bz0 = biasP[nn0], bz1 = biasP[nn0 + 1];
                    float z00 = acc[mt][j][0] + bz0;
                    float z01 = acc[mt][j][1] + bz1;
                    float z10 = acc[mt][j][2] + bz0;
                    float z11 = acc[mt][j][3] + bz1;
                    float a00, a01, a10, a11;
                    if (evenlane) { a00 = sig_a(z00);  a01 = sig_a(z01);
                                    a10 = sig_a(z10);  a11 = sig_a(z11); }
                    else          { a00 = tanhap(z00); a01 = sig_a(z01);
                                    a10 = tanhap(z10); a11 = sig_a(z11); }
                    float s1 = evenlane ? a10 : a00;
                    float s2 = evenlane ? a11 : a01;
                    float r1 = __shfl_xor_sync(~0u, s1, 1);
                    float r2 = __shfl_xor_sync(~0u, s2, 1);
                    float iv, fv, gv, ov; int rr;
                    if (evenlane) { iv = a00; fv = a01; gv = r1; ov = r2; rr = R0 + mt * 16 + ly; }
                    else          { iv = r1;  fv = r2;  gv = a10; ov = a11; rr = R0 + mt * 16 + 8 + ly; }
                    const int uu = nw * 16 + j * 2 + (kx >> 1);
                    float cc = fv * C[rr * PH + uu] + iv * gv;
                    C[rr * PH + uu] = cc;
                    float h = ov * tanhap(cc);
                    hn[rr * PH + uu] = tf32f(h);
                    if (t == LEN[rr] - 1) g_Ho[(size_t)(b0 + rr) * 128 + uu] = h;
                }
            }
        }
    }
    __syncthreads();

    // ---------------- phase C: out = relu([self | h_sel] @ We) ----------------
    for (int i = tid; i < 64 * 32; i += 256) {
        int r = i >> 5, q = i & 31;
        float4 v = *(const float4*)(self_vecs + (size_t)(b0 + r) * 128 + q * 4);
        *(float4*)(H0 + r * PH + q * 4) =
            make_float4(tf32f(v.x), tf32f(v.y), tf32f(v.z), tf32f(v.w));
        float4 h = *(const float4*)(g_Ho + (size_t)(b0 + r) * 128 + q * 4);
        *(float4*)(H1 + r * PH + q * 4) =
            make_float4(tf32f(h.x), tf32f(h.y), tf32f(h.z), tf32f(h.w));
    }
    __syncthreads();

    const int mw2 = wid & 1, nw2 = wid >> 1;   // 2m x 4n warp grid over 64 rows
    const int R2 = mw2 * 32;
    float ac2[2][4][4];
    #pragma unroll
    for (int m = 0; m < 2; m++)
        #pragma unroll
        for (int j = 0; j < 4; j++)
            #pragma unroll
            for (int e = 0; e < 4; e++) ac2[m][j][e] = 0.f;

    #pragma unroll 1
    for (int c = 0; c < 32; c++) {
        const float* bp = g_We + (c * 8 + kx) * 128 + nw2 * 32 + ly * 4;
        float4 q0 = *(const float4*)bp;
        float4 q1 = *(const float4*)(bp + 4 * 128);
        uint32_t B0[4] = {u32(q0.x), u32(q0.y), u32(q0.z), u32(q0.w)};
        uint32_t B1[4] = {u32(q1.x), u32(q1.y), u32(q1.z), u32(q1.w)};
        const float* base = (c < 16) ? H0 : H1;
        const int cc = c & 15;
        const float* ap = base + (R2 + ly) * PH + cc * 8 + kx;
        uint32_t af0[4] = {u32(ap[0]), u32(ap[8 * PH]), u32(ap[4]), u32(ap[8 * PH + 4])};
        uint32_t af1[4] = {u32(ap[16 * PH]), u32(ap[24 * PH]),
                           u32(ap[16 * PH + 4]), u32(ap[24 * PH + 4])};
        #pragma unroll
        for (int j = 0; j < 4; j++) {
            mma8(ac2[0][j], af0, B0[j], B1[j]);
            mma8(ac2[1][j], af1, B0[j], B1[j]);
        }
    }
    #pragma unroll
    for (int mt = 0; mt < 2; mt++)
        #pragma unroll
        for (int j = 0; j < 4; j++)
            #pragma unroll
            for (int rh = 0; rh < 2; rh++) {
                int row = R2 + mt * 16 + rh * 8 + ly;
                int col = nw2 * 32 + j * 8 + 2 * kx;
                float2 o;
                o.x = fmaxf(ac2[mt][j][rh * 2], 0.f);
                o.y = fmaxf(ac2[mt][j][rh * 2 + 1], 0.f);
                *(float2*)(out + (size_t)(b0 + row) * 128 + col) = o;
            }
}

extern "C" void kernel_launch(void* const* d_in, const int* in_sizes, int n_in,
                              void* d_out, int out_size) {
    prep_kernel<<<128, 512>>>((const float*)d_in[2], (const float*)d_in[3],
                              (const float*)d_in[5], (const float*)d_in[6]);
    cudaFuncSetAttribute(lstm_fused, cudaFuncAttributeMaxDynamicSharedMemorySize, SMEM_DYN);
    lstm_fused<<<256, 256, SMEM_DYN>>>((const float*)d_in[0], (const float*)d_in[1],
                                       (const float*)d_in[4], (float*)d_out);
}

// round 16
// speedup vs baseline: 1.7586x; 1.5419x over previous
#include <cuda_runtime.h>
#include <cuda_fp16.h>
#include <cstdint>

#define TT 25
#define PH 132    // fp32 smem pitch (floats): 132 % 32 == 4 -> conflict-free
#define PHH 136   // fp16 smem pitch (halves): bank = (4*ly + kx) % 32 -> conflict-free

__device__ __align__(16) uint32_t g_Wk3[32768];   // input weights fp16, B-frag order (k16)
__device__ __align__(16) uint32_t g_Wr3[32768];   // recurrent weights fp16, B-frag order
__device__ __align__(16) float g_We[256 * 128];   // output weights (tf32, frag-ordered)
__device__ float g_Ho[(size_t)16384 * 128];       // h at t = len-1
__device__ __align__(16) __half g_XW[(size_t)16384 * TT * 512];  // x@Wk, fp16 frag layout

__device__ __forceinline__ uint32_t tf32r(float v) {
    uint32_t t; asm("cvt.rna.tf32.f32 %0, %1;" : "=r"(t) : "f"(v)); return t;
}
__device__ __forceinline__ float tf32f(float v) { return __uint_as_float(tf32r(v)); }
__device__ __forceinline__ float tanhap(float x) {
    float r; asm("tanh.approx.f32 %0, %1;" : "=f"(r) : "f"(x)); return r;
}
__device__ __forceinline__ float sig_a(float x) { return fmaf(0.5f, tanhap(0.5f * x), 0.5f); }
__device__ __forceinline__ uint32_t u32(float v) { return __float_as_uint(v); }
__device__ __forceinline__ uint32_t smem_u32(const void* p) {
    uint32_t a;
    asm("{.reg .u64 t; cvta.to.shared.u64 t, %1; cvt.u32.u64 %0, t;}" : "=r"(a) : "l"(p));
    return a;
}
__device__ __forceinline__ void cp16(uint32_t dst, const float* src) {
    asm volatile("cp.async.ca.shared.global [%0],[%1],16;" :: "r"(dst), "l"(src) : "memory");
}
#define CP_COMMIT() asm volatile("cp.async.commit_group;" ::: "memory")
#define CP_WAIT0()  asm volatile("cp.async.wait_group 0;" ::: "memory")
#define CP_WAIT1()  asm volatile("cp.async.wait_group 1;" ::: "memory")

// fp16 MMA, fp32 accumulate: 16x8x16 (accumulator layout identical to tf32 k8 version)
__device__ __forceinline__ void mma16(float* d, const uint32_t* a, uint32_t b0, uint32_t b1) {
    asm volatile("mma.sync.aligned.m16n8k16.row.col.f32.f16.f16.f32 "
        "{%0,%1,%2,%3},{%4,%5,%6,%7},{%8,%9},{%0,%1,%2,%3};"
        : "+f"(d[0]), "+f"(d[1]), "+f"(d[2]), "+f"(d[3])
        : "r"(a[0]), "r"(a[1]), "r"(a[2]), "r"(a[3]), "r"(b0), "r"(b1));
}
__device__ __forceinline__ void mma8(float* d, const uint32_t* a, uint32_t b0, uint32_t b1) {
    asm volatile("mma.sync.aligned.m16n8k8.row.col.f32.tf32.tf32.f32 "
        "{%0,%1,%2,%3},{%4,%5,%6,%7},{%8,%9},{%0,%1,%2,%3};"
        : "+f"(d[0]), "+f"(d[1]), "+f"(d[2]), "+f"(d[3])
        : "r"(a[0]), "r"(a[1]), "r"(a[2]), "r"(a[3]), "r"(b0), "r"(b1));
}
__device__ __forceinline__ uint32_t packh2(float a, float b) {
    __half2 h = __floats2half2_rn(a, b);
    return *(uint32_t*)&h;
}

// fp16 B-frag layout: u32 f = (((c*4+q)*8+nw)*32+lane)*4+e ; qe=q*4+e, j=qe>>1, reg=qe&1.
// b0/b1 halves = W rows k0=c*16+2*kx+reg*8, k0+1 at gate-interleaved col n'=nw*64+j*8+ly.
__global__ void prep_kernel(const float* __restrict__ Wk, const float* __restrict__ Wr,
                            const float* __restrict__ Ws, const float* __restrict__ Wn) {
    int f = blockIdx.x * blockDim.x + threadIdx.x;   // 32768 threads
    {
        int e = f & 3, lane = (f >> 2) & 31, nw = (f >> 7) & 7, q = (f >> 10) & 3, c = f >> 12;
        int qe = q * 4 + e, j = qe >> 1, reg = qe & 1;
        int ly = lane >> 2, kx = lane & 3;
        int n = nw * 64 + j * 8 + ly;
        int col = (n & 3) * 128 + (n >> 2);
        int k0 = c * 16 + 2 * kx + reg * 8;
        g_Wk3[f] = packh2(Wk[k0 * 512 + col], Wk[(k0 + 1) * 512 + col]);
        g_Wr3[f] = packh2(Wr[k0 * 512 + col], Wr[(k0 + 1) * 512 + col]);
    }
    {   // output weights (unchanged tf32 frag layout), f < 32768 = 256*128
        int k = f >> 7, pos = f & 127;
        int nw = pos >> 5, r = pos & 31, ly = r >> 2, j = r & 3;
        int n = nw * 32 + j * 8 + ly;
        float v = (k < 128) ? Ws[k * 128 + n] : Wn[(k - 128) * 128 + n];
        g_We[k * 128 + nw * 32 + ly * 4 + j] = tf32f(v);
    }
}

#define SMEM_DYN ((3 * 64 * PH + 512 + 64) * 4)

__global__ __launch_bounds__(256, 2)
void lstm_fused(const float* __restrict__ self_vecs, const float* __restrict__ neig,
                const float* __restrict__ bias, float* __restrict__ out) {
    extern __shared__ float sm[];
    float* biasP = sm + 3 * 64 * PH;
    int* LEN = (int*)(biasP + 512);

    const int tid = threadIdx.x, wid = tid >> 5, lane = tid & 31;
    const int ly = lane >> 2, kx = lane & 3;
    const int bb = blockIdx.x, b0 = bb * 64;
    const uint32_t Xs = smem_u32(sm);

    for (int i = tid; i < 512; i += 256) biasP[i] = bias[(i & 3) * 128 + (i >> 2)];

    const int nw = wid;
    const bool evenlane = (kx & 1) == 0;

    // ---------------- phase A: g_XW = x_t @ Wk (fp16 mma), LEN from smem tiles ----------------
    __half* Xh = (__half*)(sm + 2 * 64 * PH);     // fp16 x tile [64][PHH]
    #pragma unroll
    for (int j2 = 0; j2 < 8; j2++) {              // prefetch t=0 into f32 buf 0
        int i = tid + j2 * 256;
        int r = i >> 5, q = i & 31;
        cp16(Xs + (uint32_t)(r * PH + q * 4) * 4u,
             neig + ((size_t)(b0 + r) * TT) * 128 + q * 4);
    }
    CP_COMMIT();

    int cnt[8];
    #pragma unroll
    for (int j = 0; j < 8; j++) cnt[j] = 0;

    #pragma unroll 1
    for (int t = 0; t < TT; t++) {
        if (t < TT - 1) {
            const uint32_t dstb = Xs + (uint32_t)(((t + 1) & 1) * 64 * PH) * 4u;
            #pragma unroll
            for (int j2 = 0; j2 < 8; j2++) {
                int i = tid + j2 * 256;
                int r = i >> 5, q = i & 31;
                cp16(dstb + (uint32_t)(r * PH + q * 4) * 4u,
                     neig + ((size_t)(b0 + r) * TT + t + 1) * 128 + q * 4);
            }
            CP_COMMIT();
            CP_WAIT1();
        } else {
            CP_WAIT0();
        }
        __syncthreads();
        const float* Xf = sm + (t & 1) * 64 * PH;

        // LEN from the fp32 tile (exact any-nonzero per row)
        #pragma unroll
        for (int j = 0; j < 8; j++) {
            const float* rp = Xf + (wid * 8 + j) * PH + lane;
            bool nz = (rp[0] != 0.f) || (rp[32] != 0.f) || (rp[64] != 0.f) || (rp[96] != 0.f);
            cnt[j] += (__ballot_sync(~0u, nz) != 0u);
        }
        // convert fp32 tile -> fp16 tile
        for (int i = tid; i < 64 * 32; i += 256) {
            int r = i >> 5, q = i & 31;
            float4 v = *(const float4*)(Xf + r * PH + q * 4);
            uint2 u;
            u.x = packh2(v.x, v.y); u.y = packh2(v.z, v.w);
            *(uint2*)(Xh + r * PHH + q * 4) = u;
        }
        __syncthreads();   // Xh ready

        #pragma unroll 1
        for (int p = 0; p < 2; p++) {
            const int R0 = p * 32;
            float acc[2][8][4];
            #pragma unroll
            for (int m = 0; m < 2; m++)
                #pragma unroll
                for (int j = 0; j < 8; j++)
                    #pragma unroll
                    for (int e = 0; e < 4; e++) acc[m][j][e] = 0.f;

            const uint4* wp = (const uint4*)g_Wk3 + nw * 32 + lane;
            uint4 nq0 = wp[0], nq1 = wp[256], nq2 = wp[512], nq3 = wp[768];
            #pragma unroll 1
            for (int c = 0; c < 8; c++) {
                uint4 q0 = nq0, q1 = nq1, q2 = nq2, q3 = nq3;
                if (c < 7) {
                    const uint4* np = wp + (c + 1) * 1024;
                    nq0 = np[0]; nq1 = np[256]; nq2 = np[512]; nq3 = np[768];
                }
                const __half* hp = Xh + (R0 + ly) * PHH + c * 16 + 2 * kx;
                uint32_t af0[4] = {*(const uint32_t*)hp, *(const uint32_t*)(hp + 8 * PHH),
                                   *(const uint32_t*)(hp + 8), *(const uint32_t*)(hp + 8 * PHH + 8)};
                uint32_t af1[4] = {*(const uint32_t*)(hp + 16 * PHH), *(const uint32_t*)(hp + 24 * PHH),
                                   *(const uint32_t*)(hp + 16 * PHH + 8), *(const uint32_t*)(hp + 24 * PHH + 8)};
                uint32_t Bv[16] = {q0.x, q0.y, q0.z, q0.w, q1.x, q1.y, q1.z, q1.w,
                                   q2.x, q2.y, q2.z, q2.w, q3.x, q3.y, q3.z, q3.w};
                #pragma unroll
                for (int j = 0; j < 8; j++) {
                    mma16(acc[0][j], af0, Bv[2 * j], Bv[2 * j + 1]);
                    mma16(acc[1][j], af1, Bv[2 * j], Bv[2 * j + 1]);
                }
            }
            __half* op = g_XW + ((((size_t)bb * TT + t) * 2 + p) * 8 + nw) * 2048 + lane * 4;
            #pragma unroll
            for (int i = 0; i < 16; i++) {
                uint2 v;
                v.x = packh2(acc[i >> 3][i & 7][0], acc[i >> 3][i & 7][1]);
                v.y = packh2(acc[i >> 3][i & 7][2], acc[i >> 3][i & 7][3]);
                *(uint2*)(op + i * 128) = v;
            }
        }
        __syncthreads();   // Xh reads done before next conversion; f32 buf reads done
    }
    if (lane == 0) {
        #pragma unroll
        for (int j = 0; j < 8; j++) LEN[wid * 8 + j] = cnt[j] ? cnt[j] : 1;
    }

    // ---------------- phase B: recurrence (h fp16 double buffer + fp32 C) ----------------
    __half* H0h = (__half*)sm;
    __half* H1h = H0h + 64 * PHH;
    float* Cst = sm + (2 * 64 * PHH) / 2;     // byte offset 34816 -> float index 8704
    for (int i = tid; i < 64 * PHH / 2; i += 256) ((uint32_t*)H0h)[i] = 0;
    for (int i = tid; i < 64 * PH; i += 256) Cst[i] = 0.f;

    for (int t = 0; t < TT; t++) {
        __syncthreads();
        const __half* Hc = (t & 1) ? H1h : H0h;
        __half*       Hn = (t & 1) ? H0h : H1h;

        #pragma unroll 1
        for (int p = 0; p < 2; p++) {
            const int R0 = p * 32;
            float acc[2][8][4];
            {   // acc init = own precomputed x_t@Wk fragment (fp16 -> fp32)
                const __half* xp = g_XW + ((((size_t)bb * TT + t) * 2 + p) * 8 + nw) * 2048
                                + lane * 4;
                #pragma unroll
                for (int i = 0; i < 16; i++) {
                    uint2 v = *(const uint2*)(xp + i * 128);
                    float2 f0 = __half22float2(*(__half2*)&v.x);
                    float2 f1 = __half22float2(*(__half2*)&v.y);
                    acc[i >> 3][i & 7][0] = f0.x; acc[i >> 3][i & 7][1] = f0.y;
                    acc[i >> 3][i & 7][2] = f1.x; acc[i >> 3][i & 7][3] = f1.y;
                }
            }
            const uint4* wp = (const uint4*)g_Wr3 + nw * 32 + lane;
            uint4 nq0 = wp[0], nq1 = wp[256], nq2 = wp[512], nq3 = wp[768];
            #pragma unroll 1
            for (int c = 0; c < 8; c++) {
                uint4 q0 = nq0, q1 = nq1, q2 = nq2, q3 = nq3;
                if (c < 7) {
                    const uint4* np = wp + (c + 1) * 1024;
                    nq0 = np[0]; nq1 = np[256]; nq2 = np[512]; nq3 = np[768];
                }
                const __half* hp = Hc + (R0 + ly) * PHH + c * 16 + 2 * kx;
                uint32_t af0[4] = {*(const uint32_t*)hp, *(const uint32_t*)(hp + 8 * PHH),
                                   *(const uint32_t*)(hp + 8), *(const uint32_t*)(hp + 8 * PHH + 8)};
                uint32_t af1[4] = {*(const uint32_t*)(hp + 16 * PHH), *(const uint32_t*)(hp + 24 * PHH),
                                   *(const uint32_t*)(hp + 16 * PHH + 8), *(const uint32_t*)(hp + 24 * PHH + 8)};
                uint32_t Bv[16] = {q0.x, q0.y, q0.z, q0.w, q1.x, q1.y, q1.z, q1.w,
                                   q2.x, q2.y, q2.z, q2.w, q3.x, q3.y, q3.z, q3.w};
                #pragma unroll
                for (int j = 0; j < 8; j++) {
                    mma16(acc[0][j], af0, Bv[2 * j], Bv[2 * j + 1]);
                    mma16(acc[1][j], af1, Bv[2 * j], Bv[2 * j + 1]);
                }
            }

            // ---- gate epilogue straight after own GEMM (writes Hn, no hazard) ----
            #pragma unroll
            for (int mt = 0; mt < 2; mt++) {
                #pragma unroll
                for (int j = 0; j < 8; j++) {
                    const int nn0 = nw * 64 + j * 8 + 2 * kx;
                    const float bz0 = biasP[nn0], bz1 = biasP[nn0 + 1];
                    float z00 = acc[mt][j][0] + bz0;
                    float z01 = acc[mt][j][1] + bz1;
                    float z10 = acc[mt][j][2] + bz0;
                    float z11 = acc[mt][j][3] + bz1;
                    float a00, a01, a10, a11;
                    if (evenlane) { a00 = sig_a(z00);  a01 = sig_a(z01);
                                    a10 = sig_a(z10);  a11 = sig_a(z11); }
                    else          { a00 = tanhap(z00); a01 = sig_a(z01);
                                    a10 = tanhap(z10); a11 = sig_a(z11); }
                    float s1 = evenlane ? a10 : a00;
                    float s2 = evenlane ? a11 : a01;
                    float r1 = __shfl_xor_sync(~0u, s1, 1);
                    float r2 = __shfl_xor_sync(~0u, s2, 1);
                    float iv, fv, gv, ov; int rr;
                    if (evenlane) { iv = a00; fv = a01; gv = r1; ov = r2; rr = R0 + mt * 16 + ly; }
                    else          { iv = r1;  fv = r2;  gv = a10; ov = a11; rr = R0 + mt * 16 + 8 + ly; }
                    const int uu = nw * 16 + j * 2 + (kx >> 1);
                    float cc = fv * Cst[rr * PH + uu] + iv * gv;
                    Cst[rr * PH + uu] = cc;
                    float h = ov * tanhap(cc);
                    Hn[rr * PHH + uu] = __float2half_rn(h);
                    if (t == LEN[rr] - 1) g_Ho[(size_t)(b0 + rr) * 128 + uu] = h;
                }
            }
        }
    }
    __syncthreads();

    // ---------------- phase C: out = relu([self | h_sel] @ We), tf32 mma ----------------
    float* H0 = sm;
    float* H1 = sm + 64 * PH;
    for (int i = tid; i < 64 * 32; i += 256) {
        int r = i >> 5, q = i & 31;
        float4 v = *(const float4*)(self_vecs + (size_t)(b0 + r) * 128 + q * 4);
        *(float4*)(H0 + r * PH + q * 4) =
            make_float4(tf32f(v.x), tf32f(v.y), tf32f(v.z), tf32f(v.w));
        float4 h = *(const float4*)(g_Ho + (size_t)(b0 + r) * 128 + q * 4);
        *(float4*)(H1 + r * PH + q * 4) =
            make_float4(tf32f(h.x), tf32f(h.y), tf32f(h.z), tf32f(h.w));
    }
    __syncthreads();

    const int mw2 = wid & 1, nw2 = wid >> 1;
    const int R2 = mw2 * 32;
    float ac2[2][4][4];
    #pragma unroll
    for (int m = 0; m < 2; m++)
        #pragma unroll
        for (int j = 0; j < 4; j++)
            #pragma unroll
            for (int e = 0; e < 4; e++) ac2[m][j][e] = 0.f;

    #pragma unroll 1
    for (int c = 0; c < 32; c++) {
        const float* bp = g_We + (c * 8 + kx) * 128 + nw2 * 32 + ly * 4;
        float4 q0 = *(const float4*)bp;
        float4 q1 = *(const float4*)(bp + 4 * 128);
        uint32_t B0[4] = {u32(q0.x), u32(q0.y), u32(q0.z), u32(q0.w)};
        uint32_t B1[4] = {u32(q1.x), u32(q1.y), u32(q1.z), u32(q1.w)};
        const float* base = (c < 16) ? H0 : H1;
        const int cc = c & 15;
        const float* ap = base + (R2 + ly) * PH + cc * 8 + kx;
        uint32_t af0[4] = {u32(ap[0]), u32(ap[8 * PH]), u32(ap[4]), u32(ap[8 * PH + 4])};
        uint32_t af1[4] = {u32(ap[16 * PH]), u32(ap[24 * PH]),
                           u32(ap[16 * PH + 4]), u32(ap[24 * PH + 4])};
        #pragma unroll
        for (int j = 0; j < 4; j++) {
            mma8(ac2[0][j], af0, B0[j], B1[j]);
            mma8(ac2[1][j], af1, B0[j], B1[j]);
        }
    }
    #pragma unroll
    for (int mt = 0; mt < 2; mt++)
        #pragma unroll
        for (int j = 0; j < 4; j++)
            #pragma unroll
            for (int rh = 0; rh < 2; rh++) {
                int row = R2 + mt * 16 + rh * 8 + ly;
                int col = nw2 * 32 + j * 8 + 2 * kx;
                float2 o;
                o.x = fmaxf(ac2[mt][j][rh * 2], 0.f);
                o.y = fmaxf(ac2[mt][j][rh * 2 + 1], 0.f);
                *(float2*)(out + (size_t)(b0 + row) * 128 + col) = o;
            }
}

extern "C" void kernel_launch(void* const* d_in, const int* in_sizes, int n_in,
                              void* d_out, int out_size) {
    prep_kernel<<<64, 512>>>((const float*)d_in[2], (const float*)d_in[3],
                             (const float*)d_in[5], (const float*)d_in[6]);
    cudaFuncSetAttribute(lstm_fused, cudaFuncAttributeMaxDynamicSharedMemorySize, SMEM_DYN);
    lstm_fused<<<256, 256, SMEM_DYN>>>((const float*)d_in[0], (const float*)d_in[1],
                                       (const float*)d_in[4], (float*)d_out);
}

// round 17
// speedup vs baseline: 2.1056x; 1.1973x over previous
#include <cuda_runtime.h>
#include <cuda_fp16.h>
#include <cstdint>

#define TT 25
#define PH 132    // fp32 smem pitch (floats)
#define PA2 264   // fp16 A-tile pitch (halves): 264/2 % 32 == 4 -> conflict-free

__device__ __align__(16) uint32_t g_Wc[65536];    // [Wk;Wr] fp16, B-frag order, 16 k-chunks
__device__ __align__(16) float g_We[256 * 128];   // output weights (tf32, frag-ordered)
__device__ float g_Ho[(size_t)16384 * 128];       // h at t = len-1
__device__ __align__(16) __half g_Xh[(size_t)16384 * TT * 128];  // neig in fp16
__device__ int g_LEN[16384];

__device__ __forceinline__ uint32_t tf32r(float v) {
    uint32_t t; asm("cvt.rna.tf32.f32 %0, %1;" : "=r"(t) : "f"(v)); return t;
}
__device__ __forceinline__ float tf32f(float v) { return __uint_as_float(tf32r(v)); }
__device__ __forceinline__ float tanhap(float x) {
    float r; asm("tanh.approx.f32 %0, %1;" : "=f"(r) : "f"(x)); return r;
}
__device__ __forceinline__ float sig_a(float x) { return fmaf(0.5f, tanhap(0.5f * x), 0.5f); }
__device__ __forceinline__ uint32_t u32(float v) { return __float_as_uint(v); }
__device__ __forceinline__ uint32_t smem_u32(const void* p) {
    uint32_t a;
    asm("{.reg .u64 t; cvta.to.shared.u64 t, %1; cvt.u32.u64 %0, t;}" : "=r"(a) : "l"(p));
    return a;
}
__device__ __forceinline__ void cp16(uint32_t dst, const void* src) {
    asm volatile("cp.async.ca.shared.global [%0],[%1],16;" :: "r"(dst), "l"(src) : "memory");
}
#define CP_COMMIT() asm volatile("cp.async.commit_group;" ::: "memory")
#define CP_WAIT0()  asm volatile("cp.async.wait_group 0;" ::: "memory")

__device__ __forceinline__ void mma16(float* d, const uint32_t* a, uint32_t b0, uint32_t b1) {
    asm volatile("mma.sync.aligned.m16n8k16.row.col.f32.f16.f16.f32 "
        "{%0,%1,%2,%3},{%4,%5,%6,%7},{%8,%9},{%0,%1,%2,%3};"
        : "+f"(d[0]), "+f"(d[1]), "+f"(d[2]), "+f"(d[3])
        : "r"(a[0]), "r"(a[1]), "r"(a[2]), "r"(a[3]), "r"(b0), "r"(b1));
}
__device__ __forceinline__ void mma8(float* d, const uint32_t* a, uint32_t b0, uint32_t b1) {
    asm volatile("mma.sync.aligned.m16n8k8.row.col.f32.tf32.tf32.f32 "
        "{%0,%1,%2,%3},{%4,%5,%6,%7},{%8,%9},{%0,%1,%2,%3};"
        : "+f"(d[0]), "+f"(d[1]), "+f"(d[2]), "+f"(d[3])
        : "r"(a[0]), "r"(a[1]), "r"(a[2]), "r"(a[3]), "r"(b0), "r"(b1));
}
__device__ __forceinline__ uint32_t packh2(float a, float b) {
    __half2 h = __floats2half2_rn(a, b);
    return *(uint32_t*)&h;
}

// conv kernel: neig fp32 -> g_Xh fp16 + exact g_LEN; CTAs < 256 also pack weights.
// Weight u32 slot f: e=f&3, lane=(f>>2)&31, nw=(f>>7)&7, q=(f>>10)&3, c=f>>12 (16 chunks).
// qe=q*4+e, j=qe>>1, reg=qe&1; halves = rows k0=c*16+2*kx+reg*8, k0+1 (k<128: Wk, else Wr)
// at gate-interleaved col n'=nw*64+j*8+ly -> source col (n'&3)*128+(n'>>2).
__global__ void conv_kernel(const float* __restrict__ neig,
                            const float* __restrict__ Wk, const float* __restrict__ Wr,
                            const float* __restrict__ Ws, const float* __restrict__ Wn) {
    const int tid = threadIdx.x, bx = blockIdx.x;
    if (bx < 256) {
        int f = bx * 256 + tid;
        int e = f & 3, lane = (f >> 2) & 31, nw = (f >> 7) & 7, q = (f >> 10) & 3, c = f >> 12;
        int qe = q * 4 + e, j = qe >> 1, reg = qe & 1;
        int ly = lane >> 2, kx = lane & 3;
        int n = nw * 64 + j * 8 + ly;
        int col = (n & 3) * 128 + (n >> 2);
        int k0 = c * 16 + 2 * kx + reg * 8;
        float w0 = (k0 < 128)     ? Wk[k0 * 512 + col]       : Wr[(k0 - 128) * 512 + col];
        float w1 = (k0 + 1 < 128) ? Wk[(k0 + 1) * 512 + col] : Wr[(k0 - 127) * 512 + col];
        g_Wc[f] = packh2(w0, w1);
        if (f < 32768) {   // output weights (tf32 frag layout)
            int k = f >> 7, pos = f & 127;
            int nw2 = pos >> 5, r = pos & 31, ly2 = r >> 2, j2 = r & 3;
            int n2 = nw2 * 32 + j2 * 8 + ly2;
            float v = (k < 128) ? Ws[k * 128 + n2] : Wn[(k - 128) * 128 + n2];
            g_We[k * 128 + nw2 * 32 + ly2 * 4 + j2] = tf32f(v);
        }
    }
    const int wid = tid >> 5, lane = tid & 31;
    const int b = bx * 8 + wid;                 // 2048 CTAs x 8 warps = 16384 rows
    const float4* src = (const float4*)(neig + (size_t)b * TT * 128) + lane;
    __half* dst = g_Xh + (size_t)b * TT * 128;
    int cnt = 0;
    #pragma unroll 1
    for (int t = 0; t < TT; t++) {
        float4 v = src[t * 32];
        bool nz = v.x != 0.f || v.y != 0.f || v.z != 0.f || v.w != 0.f;
        cnt += (__ballot_sync(~0u, nz) != 0u);
        uint2 u;
        u.x = packh2(v.x, v.y); u.y = packh2(v.z, v.w);
        *(uint2*)(dst + t * 128 + lane * 4) = u;
    }
    if (lane == 0) g_LEN[b] = cnt ? cnt : 1;
}

// smem bytes: T0 [0,33792) T1 [33792,67584) C [67584,101376) bias [101376,103424) LEN
#define SMEM_DYN 103936

__global__ __launch_bounds__(256, 2)
void lstm_fused(const float* __restrict__ self_vecs, const float* __restrict__ bias,
                float* __restrict__ out) {
    extern __shared__ float sm[];
    __half* T0 = (__half*)sm;                  // [64][PA2]: cols 0-127 x, 128-255 h
    __half* T1 = T0 + 64 * PA2;
    float* Cst = sm + 16896;                   // [64][PH] cell state fp32
    float* biasP = sm + 25344;                 // [512] permuted bias
    int* LEN = (int*)(sm + 25856);
    const uint32_t Ts0 = smem_u32(T0), Ts1 = smem_u32(T1);

    const int tid = threadIdx.x, wid = tid >> 5, lane = tid & 31;
    const int ly = lane >> 2, kx = lane & 3;
    const int bb = blockIdx.x, b0 = bb * 64;

    for (int i = tid; i < 512; i += 256) biasP[i] = bias[(i & 3) * 128 + (i >> 2)];
    if (tid < 64) LEN[tid] = g_LEN[b0 + tid];
    for (int i = tid; i < 64 * 64; i += 256)   // zero h region of T0
        ((uint32_t*)T0)[(i >> 6) * (PA2 / 2) + 64 + (i & 63)] = 0;
    for (int i = tid; i < 64 * PH; i += 256) Cst[i] = 0.f;

    // prefetch x_0 into T0 x-region
    #pragma unroll
    for (int j2 = 0; j2 < 4; j2++) {
        int i = tid + j2 * 256;
        int r = i >> 4, q = i & 15;
        cp16(Ts0 + (uint32_t)(r * PA2 + q * 8) * 2u,
             g_Xh + ((size_t)(b0 + r) * TT) * 128 + q * 8);
    }
    CP_COMMIT();

    const int nw = wid;
    const bool evenlane = (kx & 1) == 0;

    for (int t = 0; t < TT; t++) {
        CP_WAIT0();
        __syncthreads();   // x_t + h_t visible; prior-step tile reads done
        const __half* Tc = (t & 1) ? T1 : T0;
        __half*       Tn = (t & 1) ? T0 : T1;
        const uint32_t TnS = (t & 1) ? Ts0 : Ts1;

        if (t + 1 < TT) {   // x_{t+1} -> other tile's x-region (overlaps whole step)
            #pragma unroll
            for (int j2 = 0; j2 < 4; j2++) {
                int i = tid + j2 * 256;
                int r = i >> 4, q = i & 15;
                cp16(TnS + (uint32_t)(r * PA2 + q * 8) * 2u,
                     g_Xh + ((size_t)(b0 + r) * TT + t + 1) * 128 + q * 8);
            }
            CP_COMMIT();
        }

        #pragma unroll 1
        for (int p = 0; p < 2; p++) {
            const int R0 = p * 32;
            float acc[2][8][4];
            #pragma unroll
            for (int m = 0; m < 2; m++)
                #pragma unroll
                for (int j = 0; j < 8; j++)
                    #pragma unroll
                    for (int e = 0; e < 4; e++) acc[m][j][e] = 0.f;

            const uint4* wp = (const uint4*)g_Wc + nw * 32 + lane;
            uint4 nq0 = wp[0], nq1 = wp[256], nq2 = wp[512], nq3 = wp[768];
            #pragma unroll 1
            for (int c = 0; c < 16; c++) {
                uint4 q0 = nq0, q1 = nq1, q2 = nq2, q3 = nq3;
                if (c < 15) {
                    const uint4* np = wp + (c + 1) * 1024;
                    nq0 = np[0]; nq1 = np[256]; nq2 = np[512]; nq3 = np[768];
                }
                const __half* hp = Tc + (R0 + ly) * PA2 + c * 16 + 2 * kx;
                uint32_t af0[4] = {*(const uint32_t*)hp, *(const uint32_t*)(hp + 8 * PA2),
                                   *(const uint32_t*)(hp + 8), *(const uint32_t*)(hp + 8 * PA2 + 8)};
                uint32_t af1[4] = {*(const uint32_t*)(hp + 16 * PA2), *(const uint32_t*)(hp + 24 * PA2),
                                   *(const uint32_t*)(hp + 16 * PA2 + 8), *(const uint32_t*)(hp + 24 * PA2 + 8)};
                uint32_t Bv[16] = {q0.x, q0.y, q0.z, q0.w, q1.x, q1.y, q1.z, q1.w,
                                   q2.x, q2.y, q2.z, q2.w, q3.x, q3.y, q3.z, q3.w};
                #pragma unroll
                for (int j = 0; j < 8; j++) {
                    mma16(acc[0][j], af0, Bv[2 * j], Bv[2 * j + 1]);
                    mma16(acc[1][j], af1, Bv[2 * j], Bv[2 * j + 1]);
                }
            }

            // ---- gate epilogue (writes h_{t+1} into Tn h-cols, no hazard) ----
            #pragma unroll
            for (int mt = 0; mt < 2; mt++) {
                #pragma unroll
                for (int j = 0; j < 8; j++) {
                    const int nn0 = nw * 64 + j * 8 + 2 * kx;
                    const float bz0 = biasP[nn0], bz1 = biasP[nn0 + 1];
                    float z00 = acc[mt][j][0] + bz0;
                    float z01 = acc[mt][j][1] + bz1;
                    float z10 = acc[mt][j][2] + bz0;
                    float z11 = acc[mt][j][3] + bz1;
                    float a00, a01, a10, a11;
                    if (evenlane) { a00 = sig_a(z00);  a01 = sig_a(z01);
                                    a10 = sig_a(z10);  a11 = sig_a(z11); }
                    else          { a00 = tanhap(z00); a01 = sig_a(z01);
                                    a10 = tanhap(z10); a11 = sig_a(z11); }
                    float s1 = evenlane ? a10 : a00;
                    float s2 = evenlane ? a11 : a01;
                    float r1 = __shfl_xor_sync(~0u, s1, 1);
                    float r2 = __shfl_xor_sync(~0u, s2, 1);
                    float iv, fv, gv, ov; int rr;
                    if (evenlane) { iv = a00; fv = a01; gv = r1; ov = r2; rr = R0 + mt * 16 + ly; }
                    else          { iv = r1;  fv = r2;  gv = a10; ov = a11; rr = R0 + mt * 16 + 8 + ly; }
                    const int uu = nw * 16 + j * 2 + (kx >> 1);
                    float cc = fv * Cst[rr * PH + uu] + iv * gv;
                    Cst[rr * PH + uu] = cc;
                    float h = ov * tanhap(cc);
                    Tn[rr * PA2 + 128 + uu] = __float2half_rn(h);
                    if (t == LEN[rr] - 1) g_Ho[(size_t)(b0 + rr) * 128 + uu] = h;
                }
            }
        }
    }
    __syncthreads();

    // ---------------- phase C: out = relu([self | h_sel] @ We), tf32 mma ----------------
    float* H0 = sm;
    float* H1 = sm + 64 * PH;
    for (int i = tid; i < 64 * 32; i += 256) {
        int r = i >> 5, q = i & 31;
        float4 v = *(const float4*)(self_vecs + (size_t)(b0 + r) * 128 + q * 4);
        *(float4*)(H0 + r * PH + q * 4) =
            make_float4(tf32f(v.x), tf32f(v.y), tf32f(v.z), tf32f(v.w));
        float4 h = *(const float4*)(g_Ho + (size_t)(b0 + r) * 128 + q * 4);
        *(float4*)(H1 + r * PH + q * 4) =
            make_float4(tf32f(h.x), tf32f(h.y), tf32f(h.z), tf32f(h.w));
    }
    __syncthreads();

    const int mw2 = wid & 1, nw2 = wid >> 1;
    const int R2 = mw2 * 32;
    float ac2[2][4][4];
    #pragma unroll
    for (int m = 0; m < 2; m++)
        #pragma unroll
        for (int j = 0; j < 4; j++)
            #pragma unroll
            for (int e = 0; e < 4; e++) ac2[m][j][e] = 0.f;

    #pragma unroll 1
    for (int c = 0; c < 32; c++) {
        const float* bp = g_We + (c * 8 + kx) * 128 + nw2 * 32 + ly * 4;
        float4 q0 = *(const float4*)bp;
        float4 q1 = *(const float4*)(bp + 4 * 128);
        uint32_t B0[4] = {u32(q0.x), u32(q0.y), u32(q0.z), u32(q0.w)};
        uint32_t B1[4] = {u32(q1.x), u32(q1.y), u32(q1.z), u32(q1.w)};
        const float* base = (c < 16) ? H0 : H1;
        const int cc = c & 15;
        const float* ap = base + (R2 + ly) * PH + cc * 8 + kx;
        uint32_t af0[4] = {u32(ap[0]), u32(ap[8 * PH]), u32(ap[4]), u32(ap[8 * PH + 4])};
        uint32_t af1[4] = {u32(ap[16 * PH]), u32(ap[24 * PH]),
                           u32(ap[16 * PH + 4]), u32(ap[24 * PH + 4])};
        #pragma unroll
        for (int j = 0; j < 4; j++) {
            mma8(ac2[0][j], af0, B0[j], B1[j]);
            mma8(ac2[1][j], af1, B0[j], B1[j]);
        }
    }
    #pragma unroll
    for (int mt = 0; mt < 2; mt++)
        #pragma unroll
        for (int j = 0; j < 4; j++)
            #pragma unroll
            for (int rh = 0; rh < 2; rh++) {
                int row = R2 + mt * 16 + rh * 8 + ly;
                int col = nw2 * 32 + j * 8 + 2 * kx;
                float2 o;
                o.x = fmaxf(ac2[mt][j][rh * 2], 0.f);
                o.y = fmaxf(ac2[mt][j][rh * 2 + 1], 0.f);
                *(float2*)(out + (size_t)(b0 + row) * 128 + col) = o;
            }
}

extern "C" void kernel_launch(void* const* d_in, const int* in_sizes, int n_in,
                              void* d_out, int out_size) {
    conv_kernel<<<2048, 256>>>((const float*)d_in[1], (const float*)d_in[2],
                               (const float*)d_in[3], (const float*)d_in[5],
                               (const float*)d_in[6]);
    cudaFuncSetAttribute(lstm_fused, cudaFuncAttributeMaxDynamicSharedMemorySize, SMEM_DYN);
    lstm_fused<<<256, 256, SMEM_DYN>>>((const float*)d_in[0], (const float*)d_in[4],
                                       (float*)d_out);
}